// round 16
// baseline (speedup 1.0000x reference)
#include <cuda_runtime.h>
#include <cstdint>

#define NMAX 200000
#define H_DIM 184
#define L1_DIM 188
#define GV_DIM (H_DIM + 16)   // 200 = k-dim of W1
#define H1_BLOCKS 10
#define H1_ROWS 20            // 10*20 = 200 = GV_DIM

// Per-node accumulator: agg (4f) + deg + pad => one 32B sector, both REDs of
// an edge hit a single L2 line.
struct __align__(32) NodeAcc {
    float4 agg;
    float  deg;
    float  pad0, pad1, pad2;
};

__device__ NodeAcc      g_nd[NMAX];
__device__ float4       g_x4[NMAX];       // packed node_feat[:, :4]
__device__ unsigned int g_x1[H_DIM];      // column max of h (uint bits; h>=0)
__device__ float        g_x2[H_DIM];      // h[center]
__device__ float        g_md[16];         // md MLP output (nf-only dependency)
// REPLAY INVARIANT: g_g1 == 0 at launch entry.  First call: BSS zero.
// Every call: head2 resets it after its final read (stream-serialized).
__device__ float        g_g1[L1_DIM];

// ---------------------------------------------------------------------------
// Kernel 0: ONE pass per node: zero g_nd[i] (2 float4) + pack node_feat[:,:4]
// into g_x4[i].  md MLP on block 0 warp 0.  x1 zeroed by first H_DIM threads.
// ---------------------------------------------------------------------------
__global__ void __launch_bounds__(256) prep_kernel(
        const float* __restrict__ nf, int n_nodes,
        const int*   __restrict__ center,
        const float* __restrict__ W2,  const float* __restrict__ b2,
        const float* __restrict__ W21, const float* __restrict__ b21) {
    int stride = gridDim.x * blockDim.x;
    int tid = blockIdx.x * blockDim.x + threadIdx.x;

    // md = relu(relu(nf[c,4:6]@W2+b2)@W21+b21)  (block 0, warp 0)
    if (blockIdx.x == 0 && threadIdx.x < 32) {
        int t = threadIdx.x;
        int c = *center;
        float m0 = nf[(size_t)c * 6 + 4];
        float m1 = nf[(size_t)c * 6 + 5];
        float md1 = 0.0f;
        if (t < 16)
            md1 = fmaxf(fmaf(m0, W2[t], fmaf(m1, W2[16 + t], b2[t])), 0.0f);
        float s = (t < 16) ? b21[t] : 0.0f;
        #pragma unroll
        for (int k = 0; k < 16; k++) {
            float v = __shfl_sync(0xffffffff, md1, k);
            if (t < 16) s = fmaf(v, W21[k * 16 + t], s);
        }
        if (t < 16) g_md[t] = fmaxf(s, 0.0f);
    }

    if (tid < H_DIM) g_x1[tid] = 0u;

    const float4 z = make_float4(0.f, 0.f, 0.f, 0.f);
    for (int i = tid; i < n_nodes; i += stride) {
        const float2* p = reinterpret_cast<const float2*>(nf + (size_t)i * 6);
        float2 a = __ldg(p);
        float2 b = __ldg(p + 1);
        g_x4[i] = make_float4(a.x, a.y, b.x, b.y);
        float4* nd = reinterpret_cast<float4*>(&g_nd[i]);
        nd[0] = z;
        nd[1] = z;
    }
}

// ---------------------------------------------------------------------------
// Kernel 1: edge scatter.  One LDG.128 gather + red.v4 + red.f32, both REDs
// landing in the same 32B sector of g_nd[d].  (At the LTS-RMW floor.)
// ---------------------------------------------------------------------------
__device__ __forceinline__ void do_edge(int s, int d, float w) {
    float4 x = __ldg(&g_x4[s]);
    float* ap = reinterpret_cast<float*>(&g_nd[d]);
    asm volatile("red.global.add.v4.f32 [%0], {%1, %2, %3, %4};"
                 :: "l"(ap), "f"(x.x * w), "f"(x.y * w),
                    "f"(x.z * w), "f"(x.w * w)
                 : "memory");
    asm volatile("red.global.add.f32 [%0], %1;"
                 :: "l"(ap + 4), "f"(1.0f) : "memory");
}

__global__ void __launch_bounds__(256) edge_kernel(const int*   __restrict__ ei,
                                                   const float* __restrict__ ew, int E) {
    int i    = blockIdx.x * blockDim.x + threadIdx.x;
    int nvec = E >> 2;
    if (i < nvec) {
        int4   s = __ldcs(reinterpret_cast<const int4*>(ei) + i);
        int4   d = __ldcs(reinterpret_cast<const int4*>(ei + E) + i);
        float4 w = __ldcs(reinterpret_cast<const float4*>(ew) + i);
        do_edge(s.x, d.x, w.x);
        do_edge(s.y, d.y, w.y);
        do_edge(s.z, d.z, w.z);
        do_edge(s.w, d.w, w.w);
    }
    if (i == 0) {                                // tail (E % 4)
        for (int e = nvec * 4; e < E; e++)
            do_edge(ei[e], ei[E + e], ew[e]);
    }
}

// ---------------------------------------------------------------------------
// Kernel 1b: normalize ONCE per node: agg := agg / max(deg, 1).
// Removes all per-column rcp work (was 184x redundant MUFU) and the deg load
// from the node kernel.  Full-precision division (more accurate than rcp).
// ---------------------------------------------------------------------------
__global__ void __launch_bounds__(256) mean_kernel(int n_nodes) {
    int i = blockIdx.x * blockDim.x + threadIdx.x;
    if (i >= n_nodes) return;
    float4 agg = g_nd[i].agg;
    float  inv = 1.0f / fmaxf(g_nd[i].deg, 1.0f);
    agg.x *= inv;  agg.y *= inv;  agg.z *= inv;  agg.w *= inv;
    g_nd[i].agg = agg;
}

// ---------------------------------------------------------------------------
// Kernel 2: h = relu(b + mean@W_rel + x@W_root); 4 nodes per iteration.
// 8 FMA/(node,col) flat, no MUFU, 2 loads/node.  Per-block running max, one
// atomicMax per column.  W1/W4 L2 prefetch for the head.
// ---------------------------------------------------------------------------
__global__ void __launch_bounds__(192) node_kernel(
        const float* __restrict__ Wrel,
        const float* __restrict__ brel,
        const float* __restrict__ Wroot,
        int N, const int* __restrict__ center,
        const float* __restrict__ W1, const float* __restrict__ W4) {
    // L2 prefetch of head weights (2 lines per block, fire-and-forget)
    {
        const int W1_LINES = (GV_DIM * L1_DIM * 4 + 127) / 128;   // 1175
        int l = blockIdx.x + (int)gridDim.x * (threadIdx.x & 1);
        if (threadIdx.x < 2 && l < W1_LINES) {
            const char* p = reinterpret_cast<const char*>(W1) + (size_t)l * 128;
            asm volatile("prefetch.global.L2 [%0];" :: "l"(p));
        }
        if (blockIdx.x == 0 && threadIdx.x >= 64 && threadIdx.x < 94) {
            const char* p = reinterpret_cast<const char*>(W4)
                          + (size_t)(threadIdx.x - 64) * 128;
            asm volatile("prefetch.global.L2 [%0];" :: "l"(p));
        }
    }

    int j = threadIdx.x;
    if (j >= H_DIM) return;

    float wr0 = Wrel[j],             wr1 = Wrel[H_DIM + j];
    float wr2 = Wrel[2 * H_DIM + j], wr3 = Wrel[3 * H_DIM + j];
    float wo0 = Wroot[j],            wo1 = Wroot[H_DIM + j];
    float wo2 = Wroot[2 * H_DIM + j], wo3 = Wroot[3 * H_DIM + j];
    float bj  = brel[j];
    int   c   = *center;

    int Q = (N + 3) >> 2;
    float m = 0.0f;                              // h >= 0 after ReLU

    for (int n0 = blockIdx.x; n0 < Q; n0 += gridDim.x) {
        int n1 = n0 + Q, n2 = n0 + 2 * Q, n3 = n0 + 3 * Q;
        bool v1 = (n1 < N), v2 = (n2 < N), v3 = (n3 < N);
        int c1 = v1 ? n1 : n0, c2 = v2 ? n2 : n0, c3 = v3 ? n3 : n0;

        float4 agA = g_nd[n0].agg;  float4 xA = g_x4[n0];
        float4 agB = g_nd[c1].agg;  float4 xB = g_x4[c1];
        float4 agC = g_nd[c2].agg;  float4 xC = g_x4[c2];
        float4 agD = g_nd[c3].agg;  float4 xD = g_x4[c3];

        float hA = fmaf(agA.x, wr0, bj),  hB = fmaf(agB.x, wr0, bj);
        float hC = fmaf(agC.x, wr0, bj),  hD = fmaf(agD.x, wr0, bj);
        hA = fmaf(agA.y, wr1, hA);  hB = fmaf(agB.y, wr1, hB);
        hC = fmaf(agC.y, wr1, hC);  hD = fmaf(agD.y, wr1, hD);
        hA = fmaf(agA.z, wr2, hA);  hB = fmaf(agB.z, wr2, hB);
        hC = fmaf(agC.z, wr2, hC);  hD = fmaf(agD.z, wr2, hD);
        hA = fmaf(agA.w, wr3, hA);  hB = fmaf(agB.w, wr3, hB);
        hC = fmaf(agC.w, wr3, hC);  hD = fmaf(agD.w, wr3, hD);
        hA = fmaf(xA.x, wo0, hA);  hB = fmaf(xB.x, wo0, hB);
        hC = fmaf(xC.x, wo0, hC);  hD = fmaf(xD.x, wo0, hD);
        hA = fmaf(xA.y, wo1, hA);  hB = fmaf(xB.y, wo1, hB);
        hC = fmaf(xC.y, wo1, hC);  hD = fmaf(xD.y, wo1, hD);
        hA = fmaf(xA.z, wo2, hA);  hB = fmaf(xB.z, wo2, hB);
        hC = fmaf(xC.z, wo2, hC);  hD = fmaf(xD.z, wo2, hD);
        hA = fmaf(xA.w, wo3, hA);  hB = fmaf(xB.w, wo3, hB);
        hC = fmaf(xC.w, wo3, hC);  hD = fmaf(xD.w, wo3, hD);

        hA = fmaxf(hA, 0.0f);  hB = fmaxf(hB, 0.0f);
        hC = fmaxf(hC, 0.0f);  hD = fmaxf(hD, 0.0f);

        m = fmaxf(m, hA);
        if (v1) m = fmaxf(m, hB);
        if (v2) m = fmaxf(m, hC);
        if (v3) m = fmaxf(m, hD);

        if (n0 == c)       g_x2[j] = hA;
        if (v1 && n1 == c) g_x2[j] = hB;
        if (v2 && n2 == c) g_x2[j] = hC;
        if (v3 && n3 == c) g_x2[j] = hD;
    }
    atomicMax(&g_x1[j], __float_as_uint(m));
}

// ---------------------------------------------------------------------------
// Kernel 3a: head1 — k-split partial matvec.  Block b owns W1 rows
// [b*20, b*20+20); rows contiguous => coalesced.  One atomicAdd per thread.
// ---------------------------------------------------------------------------
__global__ void __launch_bounds__(192) head1_kernel(const float* __restrict__ W1) {
    __shared__ float gk[H1_ROWS];
    int t = threadIdx.x;
    int k0 = blockIdx.x * H1_ROWS;

    if (t < H1_ROWS) {
        int k = k0 + t;
        gk[t] = (k < H_DIM) ? (g_x2[k] - __uint_as_float(g_x1[k]))
                            : g_md[k - H_DIM];
    }
    __syncthreads();

    if (t < L1_DIM) {
        float acc = 0.0f;
        const float* w = W1 + (size_t)k0 * L1_DIM + t;
        #pragma unroll
        for (int r = 0; r < H1_ROWS; r++)
            acc = fmaf(gk[r], __ldg(w + r * L1_DIM), acc);
        atomicAdd(&g_g1[t], acc);
    }
}

// ---------------------------------------------------------------------------
// Kernel 3b: head2 — g1 = relu(g_g1 + b1); out = g1 @ W4 + b4.
// Resets g_g1 to zero after reading (replay invariant).
// ---------------------------------------------------------------------------
__global__ void __launch_bounds__(192) head2_kernel(const float* __restrict__ b1,
                                                    const float* __restrict__ W4,
                                                    const float* __restrict__ b4,
                                                    float* __restrict__ out) {
    __shared__ float g1s[L1_DIM];
    int t = threadIdx.x;
    if (t < L1_DIM) {
        g1s[t] = fmaxf(g_g1[t] + b1[t], 0.0f);
        g_g1[t] = 0.0f;                          // restore replay invariant
    }
    __syncthreads();

    if (t < 160) {
        int o    = t >> 5;                        // 0..4
        int lane = t & 31;
        float s = 0.0f;
        for (int k = lane; k < L1_DIM; k += 32)
            s = fmaf(g1s[k], __ldg(&W4[k * 5 + o]), s);
        #pragma unroll
        for (int off = 16; off > 0; off >>= 1)
            s += __shfl_down_sync(0xffffffff, s, off);
        if (lane == 0) out[o] = s + b4[o];
    }
}

// ---------------------------------------------------------------------------
extern "C" void kernel_launch(void* const* d_in, const int* in_sizes, int n_in,
                              void* d_out, int out_size) {
    const float* nf     = (const float*)d_in[0];
    const int*   ei     = (const int*)  d_in[1];
    const float* ew     = (const float*)d_in[2];
    const int*   center = (const int*)  d_in[3];
    const float* Wrel   = (const float*)d_in[4];
    const float* brel   = (const float*)d_in[5];
    const float* Wroot  = (const float*)d_in[6];
    const float* W2     = (const float*)d_in[7];
    const float* b2     = (const float*)d_in[8];
    const float* W21    = (const float*)d_in[9];
    const float* b21    = (const float*)d_in[10];
    const float* W1     = (const float*)d_in[11];
    const float* b1     = (const float*)d_in[12];
    const float* W4     = (const float*)d_in[13];
    const float* b4     = (const float*)d_in[14];
    float* out = (float*)d_out;

    int N = in_sizes[0] / 6;
    int E = in_sizes[2];

    prep_kernel<<<(N + 255) / 256, 256>>>(nf, N, center, W2, b2, W21, b21);
    int nvec = E >> 2;
    edge_kernel<<<(nvec + 255) / 256, 256>>>(ei, ew, E);
    mean_kernel<<<(N + 255) / 256, 256>>>(N);
    node_kernel<<<1024, 192>>>(Wrel, brel, Wroot, N, center, W1, W4);
    head1_kernel<<<H1_BLOCKS, 192>>>(W1);
    head2_kernel<<<1, 192>>>(b1, W4, b4, out);
}

// round 17
// speedup vs baseline: 1.3972x; 1.3972x over previous
#include <cuda_runtime.h>
#include <cstdint>

#define NMAX 200000
#define H_DIM 184
#define L1_DIM 188
#define GV_DIM (H_DIM + 16)   // 200 = k-dim of W1
#define H1_BLOCKS 10
#define H1_ROWS 20            // 10*20 = 200 = GV_DIM
#define TILE 96               // nodes staged in smem per block iteration

// Per-node accumulator: agg (4f) + deg + pad => one 32B sector, both REDs of
// an edge hit a single L2 line.
struct __align__(32) NodeAcc {
    float4 agg;
    float  deg;
    float  pad0, pad1, pad2;
};

__device__ NodeAcc      g_nd[NMAX];
__device__ float4       g_x4[NMAX];       // packed node_feat[:, :4]
__device__ unsigned int g_x1[H_DIM];      // column max of h (uint bits; h>=0)
__device__ float        g_x2[H_DIM];      // h[center]
__device__ float        g_md[16];         // md MLP output (nf-only dependency)
// REPLAY INVARIANT: g_g1 == 0 at launch entry.  First call: BSS zero.
// Every call: head2 resets it after its final read (stream-serialized).
__device__ float        g_g1[L1_DIM];

__device__ __forceinline__ float rcp_fast(float x) {
    float r;
    asm("rcp.approx.f32 %0, %1;" : "=f"(r) : "f"(x));
    return r;
}

// ---------------------------------------------------------------------------
// Kernel 0: ONE pass per node: zero g_nd[i] (2 float4) + pack node_feat[:,:4]
// into g_x4[i].  md MLP on block 0 warp 0.  x1 zeroed by first H_DIM threads.
// ---------------------------------------------------------------------------
__global__ void __launch_bounds__(256) prep_kernel(
        const float* __restrict__ nf, int n_nodes,
        const int*   __restrict__ center,
        const float* __restrict__ W2,  const float* __restrict__ b2,
        const float* __restrict__ W21, const float* __restrict__ b21) {
    int stride = gridDim.x * blockDim.x;
    int tid = blockIdx.x * blockDim.x + threadIdx.x;

    // md = relu(relu(nf[c,4:6]@W2+b2)@W21+b21)  (block 0, warp 0)
    if (blockIdx.x == 0 && threadIdx.x < 32) {
        int t = threadIdx.x;
        int c = *center;
        float m0 = nf[(size_t)c * 6 + 4];
        float m1 = nf[(size_t)c * 6 + 5];
        float md1 = 0.0f;
        if (t < 16)
            md1 = fmaxf(fmaf(m0, W2[t], fmaf(m1, W2[16 + t], b2[t])), 0.0f);
        float s = (t < 16) ? b21[t] : 0.0f;
        #pragma unroll
        for (int k = 0; k < 16; k++) {
            float v = __shfl_sync(0xffffffff, md1, k);
            if (t < 16) s = fmaf(v, W21[k * 16 + t], s);
        }
        if (t < 16) g_md[t] = fmaxf(s, 0.0f);
    }

    if (tid < H_DIM) g_x1[tid] = 0u;

    const float4 z = make_float4(0.f, 0.f, 0.f, 0.f);
    for (int i = tid; i < n_nodes; i += stride) {
        const float2* p = reinterpret_cast<const float2*>(nf + (size_t)i * 6);
        float2 a = __ldg(p);
        float2 b = __ldg(p + 1);
        g_x4[i] = make_float4(a.x, a.y, b.x, b.y);
        float4* nd = reinterpret_cast<float4*>(&g_nd[i]);
        nd[0] = z;
        nd[1] = z;
    }
}

// ---------------------------------------------------------------------------
// Kernel 1: edge scatter.  One LDG.128 gather + red.v4 + red.f32, both REDs
// landing in the same 32B sector of g_nd[d].
// ---------------------------------------------------------------------------
__device__ __forceinline__ void do_edge(int s, int d, float w) {
    float4 x = __ldg(&g_x4[s]);
    float* ap = reinterpret_cast<float*>(&g_nd[d]);
    asm volatile("red.global.add.v4.f32 [%0], {%1, %2, %3, %4};"
                 :: "l"(ap), "f"(x.x * w), "f"(x.y * w),
                    "f"(x.z * w), "f"(x.w * w)
                 : "memory");
    asm volatile("red.global.add.f32 [%0], %1;"
                 :: "l"(ap + 4), "f"(1.0f) : "memory");
}

__global__ void __launch_bounds__(256) edge_kernel(const int*   __restrict__ ei,
                                                   const float* __restrict__ ew, int E) {
    int i    = blockIdx.x * blockDim.x + threadIdx.x;
    int nvec = E >> 2;
    if (i < nvec) {
        int4   s = __ldcs(reinterpret_cast<const int4*>(ei) + i);
        int4   d = __ldcs(reinterpret_cast<const int4*>(ei + E) + i);
        float4 w = __ldcs(reinterpret_cast<const float4*>(ew) + i);
        do_edge(s.x, d.x, w.x);
        do_edge(s.y, d.y, w.y);
        do_edge(s.z, d.z, w.z);
        do_edge(s.w, d.w, w.w);
    }
    if (i == 0) {                                // tail (E % 4)
        for (int e = nvec * 4; e < E; e++)
            do_edge(ei[e], ei[E + e], ew[e]);
    }
}

// ---------------------------------------------------------------------------
// Kernel 2: SMEM-TILED node kernel.  Per tile of 96 nodes:
//   threads 0..95  : load g_nd[n].agg + deg (coalesced-ish), scale by
//                    rcp(max(deg,1)) ONCE per node, store to s_agg
//   threads 96..191: load g_x4[n] (fully coalesced) to s_x4
// then all 184 column-threads compute h over the tile from SMEM (29-cyc
// broadcast instead of 234-cyc L2 per node).  Center row handled by block 0
// outside the loop.  One atomicMax per column per block.
// ---------------------------------------------------------------------------
__global__ void __launch_bounds__(192) node_kernel(
        const float* __restrict__ Wrel,
        const float* __restrict__ brel,
        const float* __restrict__ Wroot,
        int N, const int* __restrict__ center,
        const float* __restrict__ W1, const float* __restrict__ W4) {
    __shared__ float4 s_agg[TILE];
    __shared__ float4 s_x4[TILE];

    // L2 prefetch of head weights (2 lines per block, fire-and-forget)
    {
        const int W1_LINES = (GV_DIM * L1_DIM * 4 + 127) / 128;   // 1175
        int l = blockIdx.x + (int)gridDim.x * (threadIdx.x & 1);
        if (threadIdx.x < 2 && l < W1_LINES) {
            const char* p = reinterpret_cast<const char*>(W1) + (size_t)l * 128;
            asm volatile("prefetch.global.L2 [%0];" :: "l"(p));
        }
        if (blockIdx.x == 0 && threadIdx.x >= 64 && threadIdx.x < 94) {
            const char* p = reinterpret_cast<const char*>(W4)
                          + (size_t)(threadIdx.x - 64) * 128;
            asm volatile("prefetch.global.L2 [%0];" :: "l"(p));
        }
    }

    int j = threadIdx.x;
    bool comp = (j < H_DIM);

    float wr0 = comp ? Wrel[j]             : 0.f;
    float wr1 = comp ? Wrel[H_DIM + j]     : 0.f;
    float wr2 = comp ? Wrel[2 * H_DIM + j] : 0.f;
    float wr3 = comp ? Wrel[3 * H_DIM + j] : 0.f;
    float wo0 = comp ? Wroot[j]             : 0.f;
    float wo1 = comp ? Wroot[H_DIM + j]     : 0.f;
    float wo2 = comp ? Wroot[2 * H_DIM + j] : 0.f;
    float wo3 = comp ? Wroot[3 * H_DIM + j] : 0.f;
    float bj  = comp ? brel[j] : 0.f;
    int   c   = *center;

    float m = 0.0f;                              // h >= 0 after ReLU
    int nTiles = (N + TILE - 1) / TILE;

    for (int tile = blockIdx.x; tile < nTiles; tile += gridDim.x) {
        int base = tile * TILE;
        int nt = min(TILE, N - base);
        __syncthreads();                         // smem reuse barrier
        if (j < TILE) {
            int n = base + j;
            if (n < N) {
                float4 ag = g_nd[n].agg;
                float inv = rcp_fast(fmaxf(g_nd[n].deg, 1.0f));
                ag.x *= inv;  ag.y *= inv;  ag.z *= inv;  ag.w *= inv;
                s_agg[j] = ag;
            }
        } else {
            int r = j - TILE;
            int n = base + r;
            if (n < N) s_x4[r] = g_x4[n];
        }
        __syncthreads();
        if (comp) {
            #pragma unroll 8
            for (int r = 0; r < nt; r++) {
                float4 ag = s_agg[r];
                float4 x  = s_x4[r];
                float h = fmaf(ag.x, wr0, bj);
                h = fmaf(ag.y, wr1, h);
                h = fmaf(ag.z, wr2, h);
                h = fmaf(ag.w, wr3, h);
                h = fmaf(x.x, wo0, h);
                h = fmaf(x.y, wo1, h);
                h = fmaf(x.z, wo2, h);
                h = fmaf(x.w, wo3, h);
                h = fmaxf(h, 0.0f);
                m = fmaxf(m, h);
            }
        }
    }

    // center row: computed once by block 0 (same math as loop)
    if (blockIdx.x == 0 && comp) {
        float4 ag = g_nd[c].agg;
        float inv = rcp_fast(fmaxf(g_nd[c].deg, 1.0f));
        ag.x *= inv;  ag.y *= inv;  ag.z *= inv;  ag.w *= inv;
        float4 x = g_x4[c];
        float h = fmaf(ag.x, wr0, bj);
        h = fmaf(ag.y, wr1, h);
        h = fmaf(ag.z, wr2, h);
        h = fmaf(ag.w, wr3, h);
        h = fmaf(x.x, wo0, h);
        h = fmaf(x.y, wo1, h);
        h = fmaf(x.z, wo2, h);
        h = fmaf(x.w, wo3, h);
        g_x2[j] = fmaxf(h, 0.0f);
    }

    if (comp) atomicMax(&g_x1[j], __float_as_uint(m));
}

// ---------------------------------------------------------------------------
// Kernel 3a: head1 — k-split partial matvec.  Block b owns W1 rows
// [b*20, b*20+20); rows contiguous => coalesced.  One atomicAdd per thread.
// ---------------------------------------------------------------------------
__global__ void __launch_bounds__(192) head1_kernel(const float* __restrict__ W1) {
    __shared__ float gk[H1_ROWS];
    int t = threadIdx.x;
    int k0 = blockIdx.x * H1_ROWS;

    if (t < H1_ROWS) {
        int k = k0 + t;
        gk[t] = (k < H_DIM) ? (g_x2[k] - __uint_as_float(g_x1[k]))
                            : g_md[k - H_DIM];
    }
    __syncthreads();

    if (t < L1_DIM) {
        float acc = 0.0f;
        const float* w = W1 + (size_t)k0 * L1_DIM + t;
        #pragma unroll
        for (int r = 0; r < H1_ROWS; r++)
            acc = fmaf(gk[r], __ldg(w + r * L1_DIM), acc);
        atomicAdd(&g_g1[t], acc);
    }
}

// ---------------------------------------------------------------------------
// Kernel 3b: head2 — g1 = relu(g_g1 + b1); out = g1 @ W4 + b4.
// Resets g_g1 to zero after reading (replay invariant).
// ---------------------------------------------------------------------------
__global__ void __launch_bounds__(192) head2_kernel(const float* __restrict__ b1,
                                                    const float* __restrict__ W4,
                                                    const float* __restrict__ b4,
                                                    float* __restrict__ out) {
    __shared__ float g1s[L1_DIM];
    int t = threadIdx.x;
    if (t < L1_DIM) {
        g1s[t] = fmaxf(g_g1[t] + b1[t], 0.0f);
        g_g1[t] = 0.0f;                          // restore replay invariant
    }
    __syncthreads();

    if (t < 160) {
        int o    = t >> 5;                        // 0..4
        int lane = t & 31;
        float s = 0.0f;
        for (int k = lane; k < L1_DIM; k += 32)
            s = fmaf(g1s[k], __ldg(&W4[k * 5 + o]), s);
        #pragma unroll
        for (int off = 16; off > 0; off >>= 1)
            s += __shfl_down_sync(0xffffffff, s, off);
        if (lane == 0) out[o] = s + b4[o];
    }
}

// ---------------------------------------------------------------------------
extern "C" void kernel_launch(void* const* d_in, const int* in_sizes, int n_in,
                              void* d_out, int out_size) {
    const float* nf     = (const float*)d_in[0];
    const int*   ei     = (const int*)  d_in[1];
    const float* ew     = (const float*)d_in[2];
    const int*   center = (const int*)  d_in[3];
    const float* Wrel   = (const float*)d_in[4];
    const float* brel   = (const float*)d_in[5];
    const float* Wroot  = (const float*)d_in[6];
    const float* W2     = (const float*)d_in[7];
    const float* b2     = (const float*)d_in[8];
    const float* W21    = (const float*)d_in[9];
    const float* b21    = (const float*)d_in[10];
    const float* W1     = (const float*)d_in[11];
    const float* b1     = (const float*)d_in[12];
    const float* W4     = (const float*)d_in[13];
    const float* b4     = (const float*)d_in[14];
    float* out = (float*)d_out;

    int N = in_sizes[0] / 6;
    int E = in_sizes[2];

    prep_kernel<<<(N + 255) / 256, 256>>>(nf, N, center, W2, b2, W21, b21);
    int nvec = E >> 2;
    edge_kernel<<<(nvec + 255) / 256, 256>>>(ei, ew, E);
    node_kernel<<<1024, 192>>>(Wrel, brel, Wroot, N, center, W1, W4);
    head1_kernel<<<H1_BLOCKS, 192>>>(W1);
    head2_kernel<<<1, 192>>>(b1, W4, b4, out);
}